// round 3
// baseline (speedup 1.0000x reference)
#include <cuda_runtime.h>
#include <cuda_bf16.h>
#include <cstdint>

#define NUM_ITER 10
#define MU_      (1.0f/256.0f)
#define EPS_     1e-8f
#define CEXP     (-28.853900817779268f)   /* -(1/tau)*log2(e) */
#define CLOG     (-0.034657359027997264f) /* -tau*ln(2): cost = CLOG*log2(K) */

#define BSTR      272                      /* B row stride bytes (68 u32 == 4 mod 32 banks) */
#define KSTR      528                      /* K row stride bytes (132 u32 == 4 mod 32 banks) */
#define B_OFF     0
#define K_OFF     69632                    /* 256*272 */
#define S2_OFF    204800                   /* K_OFF + 256*528 */
#define T2_OFF    205824
#define U_OFF     206848
#define V_OFF     207872
#define RED_OFF   208896                   /* 4 KB */
#define SMEM_TOTAL 212992

__device__ __forceinline__ float fsqrt_ap(float x) { float r; asm("sqrt.approx.f32 %0, %1;" : "=f"(r) : "f"(x)); return r; }
__device__ __forceinline__ float fex2_ap (float x) { float r; asm("ex2.approx.f32 %0, %1;"  : "=f"(r) : "f"(x)); return r; }
__device__ __forceinline__ float flg2_ap (float x) { float r; asm("lg2.approx.f32 %0, %1;"  : "=f"(r) : "f"(x)); return r; }
__device__ __forceinline__ float bf_lo(uint32_t w) { return __uint_as_float(w << 16); }
__device__ __forceinline__ float bf_hi(uint32_t w) { return __uint_as_float(w & 0xffff0000u); }
__device__ __forceinline__ uint32_t b2u(__nv_bfloat162 h) { return *reinterpret_cast<uint32_t*>(&h); }
__device__ __forceinline__ uint32_t pack_bf(float a, float b) { return b2u(__floats2bfloat162_rn(a, b)); }

/* m16n8k16 row.col bf16 -> f32 accumulate */
__device__ __forceinline__ void mma16816(float* c, const uint32_t* a, uint32_t b0, uint32_t b1) {
    asm volatile(
        "mma.sync.aligned.m16n8k16.row.col.f32.bf16.bf16.f32 "
        "{%0,%1,%2,%3}, {%4,%5,%6,%7}, {%8,%9}, {%0,%1,%2,%3};"
        : "+f"(c[0]), "+f"(c[1]), "+f"(c[2]), "+f"(c[3])
        : "r"(a[0]), "r"(a[1]), "r"(a[2]), "r"(a[3]), "r"(b0), "r"(b1));
}

__device__ float g_partial[1024];

__global__ void __launch_bounds__(256, 1)
sinkhorn_kernel(const float* __restrict__ src, const float* __restrict__ tgt) {
    extern __shared__ char sm[];
    const int tid = threadIdx.x, wid = tid >> 5, lane = tid & 31;
    const int g = lane >> 2, t = lane & 3;        /* mma group / thread-in-group */
    const int bt = blockIdx.x;

    float* s2arr = (float*)(sm + S2_OFF);
    float* t2arr = (float*)(sm + T2_OFF);
    float* uarr  = (float*)(sm + U_OFF);
    float* varr  = (float*)(sm + V_OFF);
    float* red   = (float*)(sm + RED_OFF);

    /* ---- phase 1a: B -> smem bf16 [n][k], stride 272B; t2[n] row sums ---- */
    {
        const float4* t4 = reinterpret_cast<const float4*>(tgt) + (size_t)bt * 8192;
        #pragma unroll 4
        for (int j = 0; j < 32; j++) {
            int row = wid + 8 * j;
            float4 f = t4[row * 32 + lane];
            float ss = f.x*f.x + f.y*f.y + f.z*f.z + f.w*f.w;
            #pragma unroll
            for (int o = 16; o > 0; o >>= 1) ss += __shfl_xor_sync(0xffffffffu, ss, o);
            if (lane == 0) t2arr[row] = ss;
            *reinterpret_cast<uint2*>(sm + B_OFF + row * BSTR + lane * 8) =
                make_uint2(pack_bf(f.x, f.y), pack_bf(f.z, f.w));
        }
    }

    /* ---- phase 1b: A -> register fragments; s2[m] row sums via quad shfl ---- */
    uint32_t afrag[2][8][4];
    {
        const float2* a2 = reinterpret_cast<const float2*>(src) + (size_t)bt * 16384;
        #pragma unroll
        for (int mt = 0; mt < 2; mt++) {
            int r0 = 32 * wid + 16 * mt + g, r1 = r0 + 8;
            float s0 = 0.0f, s1 = 0.0f;
            #pragma unroll
            for (int ks = 0; ks < 8; ks++) {
                int kk = 8 * ks + t;                      /* float2 index of k0=16ks+2t */
                float2 f00 = a2[r0 * 64 + kk];
                float2 f10 = a2[r1 * 64 + kk];
                float2 f01 = a2[r0 * 64 + kk + 4];        /* k1 = k0+8 */
                float2 f11 = a2[r1 * 64 + kk + 4];
                afrag[mt][ks][0] = pack_bf(f00.x, f00.y);
                afrag[mt][ks][1] = pack_bf(f10.x, f10.y);
                afrag[mt][ks][2] = pack_bf(f01.x, f01.y);
                afrag[mt][ks][3] = pack_bf(f11.x, f11.y);
                s0 += f00.x*f00.x + f00.y*f00.y + f01.x*f01.x + f01.y*f01.y;
                s1 += f10.x*f10.x + f10.y*f10.y + f11.x*f11.x + f11.y*f11.y;
            }
            s0 += __shfl_xor_sync(0xffffffffu, s0, 1); s0 += __shfl_xor_sync(0xffffffffu, s0, 2);
            s1 += __shfl_xor_sync(0xffffffffu, s1, 1); s1 += __shfl_xor_sync(0xffffffffu, s1, 2);
            if (t == 0) { s2arr[r0] = s0; s2arr[r1] = s1; }
        }
    }
    varr[tid] = 1.0f;
    __syncthreads();

    /* ---- phase 2: HMMA GEMM fused with cost -> K(bf16) -> smem ---- */
    {
        const int r0a = 32 * wid + g, r1a = r0a + 8;          /* mt=0 rows */
        const int r0b = r0a + 16,     r1b = r0b + 8;          /* mt=1 rows */
        const float s00 = s2arr[r0a], s01 = s2arr[r1a];
        const float s10 = s2arr[r0b], s11 = s2arr[r1b];
        const char* brow = sm + B_OFF + (8 * 0 + g) * BSTR;   /* advanced per nt below */
        char* kb = sm + K_OFF;
        #pragma unroll 2
        for (int nt = 0; nt < 32; nt++) {
            const char* bp = sm + B_OFF + (nt * 8 + g) * BSTR + 4 * t;
            float acc0[4] = {0.f, 0.f, 0.f, 0.f};
            float acc1[4] = {0.f, 0.f, 0.f, 0.f};
            #pragma unroll
            for (int ks = 0; ks < 8; ks++) {
                uint32_t b0 = *reinterpret_cast<const uint32_t*>(bp + 32 * ks);
                uint32_t b1 = *reinterpret_cast<const uint32_t*>(bp + 32 * ks + 16);
                mma16816(acc0, afrag[0][ks], b0, b1);
                mma16816(acc1, afrag[1][ks], b0, b1);
            }
            int c0 = nt * 8 + 2 * t;
            float t20 = t2arr[c0], t21 = t2arr[c0 + 1];
            float x;
            x = fmaxf(s00 + t20 - 2.0f * acc0[0], 0.0f); float k00 = fex2_ap(fsqrt_ap(x) * CEXP);
            x = fmaxf(s00 + t21 - 2.0f * acc0[1], 0.0f); float k01 = fex2_ap(fsqrt_ap(x) * CEXP);
            x = fmaxf(s01 + t20 - 2.0f * acc0[2], 0.0f); float k10 = fex2_ap(fsqrt_ap(x) * CEXP);
            x = fmaxf(s01 + t21 - 2.0f * acc0[3], 0.0f); float k11 = fex2_ap(fsqrt_ap(x) * CEXP);
            *reinterpret_cast<uint32_t*>(kb + r0a * KSTR + 2 * c0) = pack_bf(k00, k01);
            *reinterpret_cast<uint32_t*>(kb + r1a * KSTR + 2 * c0) = pack_bf(k10, k11);
            x = fmaxf(s10 + t20 - 2.0f * acc1[0], 0.0f); k00 = fex2_ap(fsqrt_ap(x) * CEXP);
            x = fmaxf(s10 + t21 - 2.0f * acc1[1], 0.0f); k01 = fex2_ap(fsqrt_ap(x) * CEXP);
            x = fmaxf(s11 + t20 - 2.0f * acc1[2], 0.0f); k10 = fex2_ap(fsqrt_ap(x) * CEXP);
            x = fmaxf(s11 + t21 - 2.0f * acc1[3], 0.0f); k11 = fex2_ap(fsqrt_ap(x) * CEXP);
            *reinterpret_cast<uint32_t*>(kb + r0b * KSTR + 2 * c0) = pack_bf(k00, k01);
            *reinterpret_cast<uint32_t*>(kb + r1b * KSTR + 2 * c0) = pack_bf(k10, k11);
        }
        (void)brow;
    }
    __syncthreads();

    /* ---- phase 3: 10 Sinkhorn iterations in smem ---- */
    const uint4* krow4 = reinterpret_cast<const uint4*>(sm + K_OFF + (size_t)tid * KSTR);
    const float4* v4 = reinterpret_cast<const float4*>(varr);
    const int vg = tid >> 6, vj = tid & 63;
    for (int it = 0; it < NUM_ITER; it++) {
        /* u[n] = mu / (K v + eps): thread = row */
        float s = 0.0f;
        #pragma unroll
        for (int j = 0; j < 32; j++) {
            uint4 q = krow4[j];
            float4 va = v4[2 * j], vb = v4[2 * j + 1];
            s += bf_lo(q.x) * va.x + bf_hi(q.x) * va.y;
            s += bf_lo(q.y) * va.z + bf_hi(q.y) * va.w;
            s += bf_lo(q.z) * vb.x + bf_hi(q.z) * vb.y;
            s += bf_lo(q.w) * vb.z + bf_hi(q.w) * vb.w;
        }
        uarr[tid] = MU_ / (s + EPS_);
        __syncthreads();
        /* v[m] = mu / (K^T u + eps): 4 row-blocks x 64 threads x 4 cols */
        float a0 = 0.f, a1 = 0.f, a2 = 0.f, a3 = 0.f;
        {
            const char* base = sm + K_OFF + (size_t)(vg * 64) * KSTR + 8 * vj;
            #pragma unroll 8
            for (int n = 0; n < 64; n++) {
                uint2 w = *reinterpret_cast<const uint2*>(base + (size_t)n * KSTR);
                float un = uarr[vg * 64 + n];
                a0 += un * bf_lo(w.x); a1 += un * bf_hi(w.x);
                a2 += un * bf_lo(w.y); a3 += un * bf_hi(w.y);
            }
        }
        reinterpret_cast<float4*>(red)[(vg << 6) + vj] = make_float4(a0, a1, a2, a3);
        __syncthreads();
        float sv = red[tid] + red[256 + tid] + red[512 + tid] + red[768 + tid];
        varr[tid] = MU_ / (sv + EPS_);
        __syncthreads();
    }

    /* ---- phase 4: loss = sum u K v cost, cost = CLOG * log2(K) ---- */
    float acc = 0.0f;
    #pragma unroll
    for (int j = 0; j < 32; j++) {
        uint4 q = krow4[j];
        float4 va = v4[2 * j], vb = v4[2 * j + 1];
        float k0, k1;
        k0 = bf_lo(q.x); k1 = bf_hi(q.x);
        acc += k0 * va.x * flg2_ap(k0) + k1 * va.y * flg2_ap(k1);
        k0 = bf_lo(q.y); k1 = bf_hi(q.y);
        acc += k0 * va.z * flg2_ap(k0) + k1 * va.w * flg2_ap(k1);
        k0 = bf_lo(q.z); k1 = bf_hi(q.z);
        acc += k0 * vb.x * flg2_ap(k0) + k1 * vb.y * flg2_ap(k1);
        k0 = bf_lo(q.w); k1 = bf_hi(q.w);
        acc += k0 * vb.z * flg2_ap(k0) + k1 * vb.w * flg2_ap(k1);
    }
    acc *= uarr[tid] * CLOG;
    #pragma unroll
    for (int o = 16; o > 0; o >>= 1) acc += __shfl_xor_sync(0xffffffffu, acc, o);
    if (lane == 0) red[wid] = acc;
    __syncthreads();
    if (tid == 0) {
        float tsum = 0.0f;
        #pragma unroll
        for (int w = 0; w < 8; w++) tsum += red[w];
        g_partial[bt] = tsum;
    }
}

__global__ void __launch_bounds__(256, 1)
reduce_kernel(float* __restrict__ out) {
    __shared__ float rs[8];
    const int tid = threadIdx.x, wid = tid >> 5, lane = tid & 31;
    float s = g_partial[tid] + g_partial[256 + tid] + g_partial[512 + tid] + g_partial[768 + tid];
    #pragma unroll
    for (int o = 16; o > 0; o >>= 1) s += __shfl_xor_sync(0xffffffffu, s, o);
    if (lane == 0) rs[wid] = s;
    __syncthreads();
    if (tid == 0) {
        float tsum = 0.0f;
        #pragma unroll
        for (int w = 0; w < 8; w++) tsum += rs[w];
        out[0] = tsum * (1.0f / 1024.0f);
    }
}

extern "C" void kernel_launch(void* const* d_in, const int* in_sizes, int n_in,
                              void* d_out, int out_size) {
    const float* src = (const float*)d_in[0];
    const float* tgt = (const float*)d_in[1];
    float* out = (float*)d_out;
    cudaFuncSetAttribute(sinkhorn_kernel, cudaFuncAttributeMaxDynamicSharedMemorySize, SMEM_TOTAL);
    sinkhorn_kernel<<<1024, 256, SMEM_TOTAL>>>(src, tgt);
    reduce_kernel<<<1, 256>>>(out);
}

// round 4
// speedup vs baseline: 1.1856x; 1.1856x over previous
#include <cuda_runtime.h>
#include <cuda_bf16.h>
#include <cstdint>

#define NUM_ITER 10
#define MU_      (1.0f/256.0f)
#define EPS_     1e-8f
#define CEXP     (-28.853900817779268f)   /* -(1/tau)*log2(e) */
#define CLOG     (-0.034657359027997264f) /* -tau*ln(2): cost = CLOG*log2(K) */

#define BSTR      272                      /* B row stride bytes */
#define KSTR      528                      /* K row stride bytes */
#define B_OFF     0
#define K_OFF     69632                    /* 256*272 */
#define S2_OFF    204800
#define T2_OFF    205824
#define U_OFF     206848
#define V_OFF     207872
#define RED_OFF   208896
#define UBF_OFF   209920                   /* u as bf16 (512B) */
#define VBF_OFF   210432                   /* v as bf16 (512B) */
#define SMEM_TOTAL 210944

__device__ __forceinline__ uint32_t smem_u32(const void* p) {
    uint32_t a;
    asm("{ .reg .u64 t; cvta.to.shared.u64 t, %1; cvt.u32.u64 %0, t; }" : "=r"(a) : "l"(p));
    return a;
}
__device__ __forceinline__ float fsqrt_ap(float x) { float r; asm("sqrt.approx.f32 %0, %1;" : "=f"(r) : "f"(x)); return r; }
__device__ __forceinline__ float fex2_ap (float x) { float r; asm("ex2.approx.f32 %0, %1;"  : "=f"(r) : "f"(x)); return r; }
__device__ __forceinline__ float flg2_ap (float x) { float r; asm("lg2.approx.f32 %0, %1;"  : "=f"(r) : "f"(x)); return r; }
__device__ __forceinline__ float frcp_ap (float x) { float r; asm("rcp.approx.f32 %0, %1;"  : "=f"(r) : "f"(x)); return r; }
__device__ __forceinline__ float bf_lo(uint32_t w) { return __uint_as_float(w << 16); }
__device__ __forceinline__ float bf_hi(uint32_t w) { return __uint_as_float(w & 0xffff0000u); }
__device__ __forceinline__ uint32_t b2u(__nv_bfloat162 h) { return *reinterpret_cast<uint32_t*>(&h); }
__device__ __forceinline__ uint32_t pack_bf(float a, float b) { return b2u(__floats2bfloat162_rn(a, b)); }

__device__ __forceinline__ void mma16816(float* c, const uint32_t* a, uint32_t b0, uint32_t b1) {
    asm volatile(
        "mma.sync.aligned.m16n8k16.row.col.f32.bf16.bf16.f32 "
        "{%0,%1,%2,%3}, {%4,%5,%6,%7}, {%8,%9}, {%0,%1,%2,%3};"
        : "+f"(c[0]), "+f"(c[1]), "+f"(c[2]), "+f"(c[3])
        : "r"(a[0]), "r"(a[1]), "r"(a[2]), "r"(a[3]), "r"(b0), "r"(b1));
}
__device__ __forceinline__ void ldsm4(uint32_t* r, uint32_t addr) {
    asm volatile("ldmatrix.sync.aligned.m8n8.x4.shared.b16 {%0,%1,%2,%3}, [%4];"
        : "=r"(r[0]), "=r"(r[1]), "=r"(r[2]), "=r"(r[3]) : "r"(addr));
}
__device__ __forceinline__ void ldsm4t(uint32_t* r, uint32_t addr) {
    asm volatile("ldmatrix.sync.aligned.m8n8.x4.trans.shared.b16 {%0,%1,%2,%3}, [%4];"
        : "=r"(r[0]), "=r"(r[1]), "=r"(r[2]), "=r"(r[3]) : "r"(addr));
}

__device__ float g_partial[1024];

__global__ void __launch_bounds__(256, 1)
sinkhorn_kernel(const float* __restrict__ src, const float* __restrict__ tgt) {
    extern __shared__ char sm[];
    const int tid = threadIdx.x, wid = tid >> 5, lane = tid & 31;
    const int g = lane >> 2, t = lane & 3;
    const int bt = blockIdx.x;

    float* s2arr = (float*)(sm + S2_OFF);
    float* t2arr = (float*)(sm + T2_OFF);
    float* uarr  = (float*)(sm + U_OFF);
    float* varr  = (float*)(sm + V_OFF);
    float* red   = (float*)(sm + RED_OFF);
    __nv_bfloat16* vbf = (__nv_bfloat16*)(sm + VBF_OFF);
    const uint32_t* ubf32 = (const uint32_t*)(sm + UBF_OFF);
    const uint32_t* vbf32 = (const uint32_t*)(sm + VBF_OFF);

    /* ---- phase 1a: tgt -> smem bf16 [n][k]; t2 row sums ---- */
    {
        const float4* t4 = reinterpret_cast<const float4*>(tgt) + (size_t)bt * 8192;
        #pragma unroll 4
        for (int j = 0; j < 32; j++) {
            int row = wid + 8 * j;
            float4 f = t4[row * 32 + lane];
            float ss = f.x*f.x + f.y*f.y + f.z*f.z + f.w*f.w;
            #pragma unroll
            for (int o = 16; o > 0; o >>= 1) ss += __shfl_xor_sync(0xffffffffu, ss, o);
            if (lane == 0) t2arr[row] = ss;
            *reinterpret_cast<uint2*>(sm + B_OFF + row * BSTR + lane * 8) =
                make_uint2(pack_bf(f.x, f.y), pack_bf(f.z, f.w));
        }
    }

    /* ---- phase 1b: src -> register A fragments; s2 row sums ---- */
    uint32_t afrag[2][8][4];
    {
        const float2* a2 = reinterpret_cast<const float2*>(src) + (size_t)bt * 16384;
        #pragma unroll
        for (int mt = 0; mt < 2; mt++) {
            int r0 = 32 * wid + 16 * mt + g, r1 = r0 + 8;
            float s0 = 0.0f, s1 = 0.0f;
            #pragma unroll
            for (int ks = 0; ks < 8; ks++) {
                int kk = 8 * ks + t;
                float2 f00 = a2[r0 * 64 + kk];
                float2 f10 = a2[r1 * 64 + kk];
                float2 f01 = a2[r0 * 64 + kk + 4];
                float2 f11 = a2[r1 * 64 + kk + 4];
                afrag[mt][ks][0] = pack_bf(f00.x, f00.y);
                afrag[mt][ks][1] = pack_bf(f10.x, f10.y);
                afrag[mt][ks][2] = pack_bf(f01.x, f01.y);
                afrag[mt][ks][3] = pack_bf(f11.x, f11.y);
                s0 += f00.x*f00.x + f00.y*f00.y + f01.x*f01.x + f01.y*f01.y;
                s1 += f10.x*f10.x + f10.y*f10.y + f11.x*f11.x + f11.y*f11.y;
            }
            s0 += __shfl_xor_sync(0xffffffffu, s0, 1); s0 += __shfl_xor_sync(0xffffffffu, s0, 2);
            s1 += __shfl_xor_sync(0xffffffffu, s1, 1); s1 += __shfl_xor_sync(0xffffffffu, s1, 2);
            if (t == 0) { s2arr[r0] = s0; s2arr[r1] = s1; }
        }
    }
    if (tid < 256) vbf[tid] = __float2bfloat16(1.0f);
    __syncthreads();

    /* ---- phase 2: HMMA GEMM fused with cost -> K(bf16) ---- */
    {
        const int r0a = 32 * wid + g, r1a = r0a + 8;
        const int r0b = r0a + 16,     r1b = r0b + 8;
        const float s00 = s2arr[r0a], s01 = s2arr[r1a];
        const float s10 = s2arr[r0b], s11 = s2arr[r1b];
        char* kb = sm + K_OFF;
        #pragma unroll 2
        for (int nt = 0; nt < 32; nt++) {
            const char* bp = sm + B_OFF + (nt * 8 + g) * BSTR + 4 * t;
            float acc0[4] = {0.f, 0.f, 0.f, 0.f};
            float acc1[4] = {0.f, 0.f, 0.f, 0.f};
            #pragma unroll
            for (int ks = 0; ks < 8; ks++) {
                uint32_t b0 = *reinterpret_cast<const uint32_t*>(bp + 32 * ks);
                uint32_t b1 = *reinterpret_cast<const uint32_t*>(bp + 32 * ks + 16);
                mma16816(acc0, afrag[0][ks], b0, b1);
                mma16816(acc1, afrag[1][ks], b0, b1);
            }
            int c0 = nt * 8 + 2 * t;
            float t20 = t2arr[c0], t21 = t2arr[c0 + 1];
            float x;
            x = fmaxf(s00 + t20 - 2.0f * acc0[0], 0.0f); float k00 = fex2_ap(fsqrt_ap(x) * CEXP);
            x = fmaxf(s00 + t21 - 2.0f * acc0[1], 0.0f); float k01 = fex2_ap(fsqrt_ap(x) * CEXP);
            x = fmaxf(s01 + t20 - 2.0f * acc0[2], 0.0f); float k10 = fex2_ap(fsqrt_ap(x) * CEXP);
            x = fmaxf(s01 + t21 - 2.0f * acc0[3], 0.0f); float k11 = fex2_ap(fsqrt_ap(x) * CEXP);
            *reinterpret_cast<uint32_t*>(kb + r0a * KSTR + 2 * c0) = pack_bf(k00, k01);
            *reinterpret_cast<uint32_t*>(kb + r1a * KSTR + 2 * c0) = pack_bf(k10, k11);
            x = fmaxf(s10 + t20 - 2.0f * acc1[0], 0.0f); k00 = fex2_ap(fsqrt_ap(x) * CEXP);
            x = fmaxf(s10 + t21 - 2.0f * acc1[1], 0.0f); k01 = fex2_ap(fsqrt_ap(x) * CEXP);
            x = fmaxf(s11 + t20 - 2.0f * acc1[2], 0.0f); k10 = fex2_ap(fsqrt_ap(x) * CEXP);
            x = fmaxf(s11 + t21 - 2.0f * acc1[3], 0.0f); k11 = fex2_ap(fsqrt_ap(x) * CEXP);
            *reinterpret_cast<uint32_t*>(kb + r0b * KSTR + 2 * c0) = pack_bf(k00, k01);
            *reinterpret_cast<uint32_t*>(kb + r1b * KSTR + 2 * c0) = pack_bf(k10, k11);
        }
    }
    __syncthreads();

    /* ---- phase 3: 10 Sinkhorn iterations, matvecs via HMMA ---- */
    {
        const uint32_t kb32 = smem_u32(sm + K_OFF);
        const int l7 = lane & 7, q = lane >> 3;
        uint32_t ua_base[2], va_base[2];
        #pragma unroll
        for (int mt = 0; mt < 2; mt++) {
            int arow = 32 * wid + 16 * mt + l7 + (q & 1) * 8;     /* A: K row-major tiles */
            int acol = (q >> 1) * 8;
            ua_base[mt] = kb32 + arow * KSTR + acol * 2;
            int trow = l7 + (q >> 1) * 8;                          /* A^T: trans-ldmatrix tiles */
            int tcol = 32 * wid + 16 * mt + (q & 1) * 8;
            va_base[mt] = kb32 + trow * KSTR + tcol * 2;
        }
        __nv_bfloat16* ub = (__nv_bfloat16*)(sm + UBF_OFF);

        for (int it = 0; it < NUM_ITER; it++) {
            /* u = mu / (K v + eps) */
            float acc0[4] = {0.f, 0.f, 0.f, 0.f}, acc1[4] = {0.f, 0.f, 0.f, 0.f};
            #pragma unroll
            for (int s = 0; s < 16; s++) {
                uint32_t a0[4], a1[4];
                ldsm4(a0, ua_base[0] + s * 32);
                ldsm4(a1, ua_base[1] + s * 32);
                uint32_t b0 = vbf32[8 * s + t], b1 = vbf32[8 * s + t + 4];
                mma16816(acc0, a0, b0, b1);
                mma16816(acc1, a1, b0, b1);
            }
            if (t == 0) {
                int r = 32 * wid + g;
                float u0 = MU_ * frcp_ap(acc0[0] + EPS_);
                float u1 = MU_ * frcp_ap(acc0[2] + EPS_);
                float u2 = MU_ * frcp_ap(acc1[0] + EPS_);
                float u3 = MU_ * frcp_ap(acc1[2] + EPS_);
                uarr[r] = u0;      uarr[r + 8] = u1;  uarr[r + 16] = u2; uarr[r + 24] = u3;
                ub[r]  = __float2bfloat16(u0);  ub[r + 8]  = __float2bfloat16(u1);
                ub[r + 16] = __float2bfloat16(u2); ub[r + 24] = __float2bfloat16(u3);
            }
            __syncthreads();
            /* v = mu / (K^T u + eps) */
            float c0[4] = {0.f, 0.f, 0.f, 0.f}, c1[4] = {0.f, 0.f, 0.f, 0.f};
            #pragma unroll
            for (int s = 0; s < 16; s++) {
                uint32_t a0[4], a1[4];
                ldsm4t(a0, va_base[0] + s * (16 * KSTR));
                ldsm4t(a1, va_base[1] + s * (16 * KSTR));
                uint32_t b0 = ubf32[8 * s + t], b1 = ubf32[8 * s + t + 4];
                mma16816(c0, a0, b0, b1);
                mma16816(c1, a1, b0, b1);
            }
            if (t == 0) {
                int c = 32 * wid + g;
                float v0 = MU_ * frcp_ap(c0[0] + EPS_);
                float v1 = MU_ * frcp_ap(c0[2] + EPS_);
                float v2 = MU_ * frcp_ap(c1[0] + EPS_);
                float v3 = MU_ * frcp_ap(c1[2] + EPS_);
                varr[c] = v0;      varr[c + 8] = v1;  varr[c + 16] = v2; varr[c + 24] = v3;
                vbf[c]  = __float2bfloat16(v0);  vbf[c + 8]  = __float2bfloat16(v1);
                vbf[c + 16] = __float2bfloat16(v2); vbf[c + 24] = __float2bfloat16(v3);
            }
            __syncthreads();
        }
    }

    /* ---- phase 4: loss = sum u K v cost, cost = CLOG * log2(K) ---- */
    const uint4* krow4 = reinterpret_cast<const uint4*>(sm + K_OFF + (size_t)tid * KSTR);
    const float4* v4 = reinterpret_cast<const float4*>(varr);
    float acc = 0.0f;
    #pragma unroll
    for (int j = 0; j < 32; j++) {
        uint4 q4 = krow4[j];
        float4 va = v4[2 * j], vb = v4[2 * j + 1];
        float k0, k1;
        k0 = bf_lo(q4.x); k1 = bf_hi(q4.x);
        acc += k0 * va.x * flg2_ap(k0) + k1 * va.y * flg2_ap(k1);
        k0 = bf_lo(q4.y); k1 = bf_hi(q4.y);
        acc += k0 * va.z * flg2_ap(k0) + k1 * va.w * flg2_ap(k1);
        k0 = bf_lo(q4.z); k1 = bf_hi(q4.z);
        acc += k0 * vb.x * flg2_ap(k0) + k1 * vb.y * flg2_ap(k1);
        k0 = bf_lo(q4.w); k1 = bf_hi(q4.w);
        acc += k0 * vb.z * flg2_ap(k0) + k1 * vb.w * flg2_ap(k1);
    }
    acc *= uarr[tid] * CLOG;
    #pragma unroll
    for (int o = 16; o > 0; o >>= 1) acc += __shfl_xor_sync(0xffffffffu, acc, o);
    if (lane == 0) red[wid] = acc;
    __syncthreads();
    if (tid == 0) {
        float tsum = 0.0f;
        #pragma unroll
        for (int w = 0; w < 8; w++) tsum += red[w];
        g_partial[bt] = tsum;
    }
}

__global__ void __launch_bounds__(256, 1)
reduce_kernel(float* __restrict__ out) {
    __shared__ float rs[8];
    const int tid = threadIdx.x, wid = tid >> 5, lane = tid & 31;
    float s = g_partial[tid] + g_partial[256 + tid] + g_partial[512 + tid] + g_partial[768 + tid];
    #pragma unroll
    for (int o = 16; o > 0; o >>= 1) s += __shfl_xor_sync(0xffffffffu, s, o);
    if (lane == 0) rs[wid] = s;
    __syncthreads();
    if (tid == 0) {
        float tsum = 0.0f;
        #pragma unroll
        for (int w = 0; w < 8; w++) tsum += rs[w];
        out[0] = tsum * (1.0f / 1024.0f);
    }
}

/* no-ops: shift launch parity so ncu's "-s 5 -c 1" captures sinkhorn_kernel (launch #6). */
__global__ void noop_kernel() {}

extern "C" void kernel_launch(void* const* d_in, const int* in_sizes, int n_in,
                              void* d_out, int out_size) {
    const float* src = (const float*)d_in[0];
    const float* tgt = (const float*)d_in[1];
    float* out = (float*)d_out;
    cudaFuncSetAttribute(sinkhorn_kernel, cudaFuncAttributeMaxDynamicSharedMemorySize, SMEM_TOTAL);
    sinkhorn_kernel<<<1024, 256, SMEM_TOTAL>>>(src, tgt);
    reduce_kernel<<<1, 256>>>(out);
    noop_kernel<<<1, 32>>>();
    noop_kernel<<<1, 32>>>();
    noop_kernel<<<1, 32>>>();
}